// round 16
// baseline (speedup 1.0000x reference)
#include <cuda_runtime.h>
#include <cuda_fp16.h>
#include <cstdint>
#include <math.h>

#define SEQ 4096
#define DIM 1024

// Scratch (allocation-free rule: device globals)
__device__ __half g_xh[SEQ * DIM];            // fp16 x
__device__ __half g_wqkh[2 * DIM * DIM];      // fp16 [Wq; Wk] packed
__device__ __half g_wvh[DIM * DIM];           // fp16 Wv
__device__ __half g_qkh[SEQ * 2 * DIM];       // [Q | K] fp16, ld = 2048
__device__ __half g_vth[(size_t)DIM * SEQ];   // V^T fp16 [1024, 4096]
__device__ __half g_ph[(size_t)SEQ * SEQ];    // exp(S) fp16 (unnormalized P)
__device__ float  g_rsum[SEQ];                // rowsum of P (atomic accum)

// ---------------------------------------------------------------------------
// PTX helpers (base-target-safe: cp.async + mma.sync + ldmatrix only)
// ---------------------------------------------------------------------------
__device__ __forceinline__ uint32_t smem_u32(const void* p) {
    uint32_t a;
    asm("{ .reg .u64 t; cvta.to.shared.u64 t, %1; cvt.u32.u64 %0, t; }" : "=r"(a) : "l"(p));
    return a;
}
__device__ __forceinline__ void cp16(uint32_t s, const void* g) {
    asm volatile("cp.async.cg.shared.global [%0], [%1], 16;" :: "r"(s), "l"(g));
}
__device__ __forceinline__ void cp_commit() {
    asm volatile("cp.async.commit_group;" ::: "memory");
}
__device__ __forceinline__ void ldmx4(uint32_t* r, uint32_t addr) {
    asm volatile("ldmatrix.sync.aligned.m8n8.x4.shared.b16 {%0,%1,%2,%3}, [%4];"
        : "=r"(r[0]), "=r"(r[1]), "=r"(r[2]), "=r"(r[3]) : "r"(addr));
}
__device__ __forceinline__ void mma_f16(float* c, const uint32_t* a, const uint32_t* b) {
    asm volatile(
        "mma.sync.aligned.m16n8k16.row.col.f32.f16.f16.f32 "
        "{%0,%1,%2,%3}, {%4,%5,%6,%7}, {%8,%9}, {%0,%1,%2,%3};"
        : "+f"(c[0]), "+f"(c[1]), "+f"(c[2]), "+f"(c[3])
        : "r"(a[0]), "r"(a[1]), "r"(a[2]), "r"(a[3]), "r"(b[0]), "r"(b[1]));
}

// ---------------------------------------------------------------------------
// Merged fp32 -> fp16 conversion of x, Wq, Wk, Wv + rsum zero + out zero
// ---------------------------------------------------------------------------
#define XN4   (SEQ * DIM / 4)      // 1048576
#define WN4   (DIM * DIM / 4)      // 262144
__global__ __launch_bounds__(256)
void cvt_all(const float* __restrict__ x,  const float* __restrict__ Wq,
             const float* __restrict__ Wk, const float* __restrict__ Wv,
             __half* __restrict__ xh, __half* __restrict__ wqkh,
             __half* __restrict__ wvh, float* __restrict__ rs,
             float* __restrict__ outz)
{
    int i = blockIdx.x * 256 + threadIdx.x;
    if (i < SEQ) rs[i] = 0.0f;      // deterministic rsum zero for graph replay
    if (i < XN4)                    // zero out (split-K atomic accumulation base)
        ((float4*)outz)[i] = make_float4(0.0f, 0.0f, 0.0f, 0.0f);
    const float* src;
    __half* dst;
    int off;
    if (i < XN4)                 { src = x;  dst = xh;   off = i; }
    else if (i < XN4 + WN4)      { src = Wq; dst = wqkh; off = i - XN4; }
    else if (i < XN4 + 2 * WN4)  { src = Wk; dst = wqkh + DIM * DIM; off = i - XN4 - WN4; }
    else if (i < XN4 + 3 * WN4)  { src = Wv; dst = wvh;  off = i - XN4 - 2 * WN4; }
    else return;
    float4 v = ((const float4*)src)[off];
    __half2* o = (__half2*)dst + 2 * (size_t)off;
    o[0] = __floats2half2_rn(v.x, v.y);
    o[1] = __floats2half2_rn(v.z, v.w);
}

// ---------------------------------------------------------------------------
// fp16 mma.sync NT GEMM body: C[M,N] = epi(scale * A[M,K] * B^T)
// BM=BN=128, BK=32, 4-stage cp.async (1 sync/iter), 128 threads, 4 warps (2x2),
// 64x64 per warp, ldmatrix.x4 fragments, m16n8k16 HMMA, fp32 accumulate.
// 2 CTAs/SM. (PROVEN mainloop — do not restructure: R5/R11/R12/R15 all lost.)
// EPI: 0 = fp32 store, 1 = fp16 store, 2 = fp16 exp(scale*acc) + rowsum atomics,
//      3 = fp32 atomicAdd (split-K partial; exactly 2 partials -> deterministic).
// DIV: multiply output rows by 1/rsum[r] (EPI=0/3 paths).
// ---------------------------------------------------------------------------
#define SW 20                       // smem words per 32-half row (16 used + 4 pad)
#define TILE_W (128 * SW)           // words per A (or B) tile = 2560
#define NSTG 4
#define SMEM_BYTES (NSTG * 2 * TILE_W * 4)   // 81920

template <int EPI, bool DIV>
__device__ __forceinline__
void gemm_body(const __half* __restrict__ A, const __half* __restrict__ B,
               void* __restrict__ Cv, int K, int lda, int ldb, int ldc,
               float scale, float* __restrict__ rsum, int row0, int col0)
{
    extern __shared__ float sm[];
    const int tid  = threadIdx.x;
    const int lane = tid & 31;
    const int wid  = tid >> 5;     // 0..3
    const int gid  = lane >> 2;    // 0..7
    const int tig  = lane & 3;     // 0..3
    const int wm   = (wid & 1) * 64;
    const int wn   = (wid >> 1) * 64;

    const uint32_t sm0 = smem_u32(sm);

    // ldmatrix per-lane address offsets (bytes), within a stage
    const int mat = lane >> 3;     // 0..3
    const int rim = lane & 7;      // row in 8x8 matrix
    uint32_t aOff[4], bOff[4];
#pragma unroll
    for (int mt = 0; mt < 4; mt++)  // A m16 tile: row += (mat&1)*8, kw += (mat>>1)*4
        aOff[mt] = (uint32_t)(((wm + mt * 16 + (mat & 1) * 8 + rim) * SW
                               + (mat >> 1) * 4) * 4);
#pragma unroll
    for (int p = 0; p < 4; p++)     // B nt-pair: row += (mat>>1)*8, kw += (mat&1)*4
        bOff[p] = (uint32_t)((TILE_W + (wn + p * 16 + (mat >> 1) * 8 + rim) * SW
                               + (mat & 1) * 4) * 4);

    float acc[4][8][4];
#pragma unroll
    for (int i = 0; i < 4; i++)
#pragma unroll
        for (int j = 0; j < 8; j++)
#pragma unroll
            for (int q = 0; q < 4; q++) acc[i][j][q] = 0.0f;

    const int KT = K >> 5;   // K / 32

    auto issue = [&](int slot, int kt) {
        const uint32_t sa = sm0 + (slot * 2 * TILE_W) * 4;
        const uint32_t sb = sa + TILE_W * 4;
        const int kb = kt * 32;
#pragma unroll
        for (int t = 0; t < 4; t++) {
            int idx = tid + t * 128;          // 0..511
            int r = idx >> 2, c = idx & 3;    // row, 16B-chunk
            cp16(sa + (r * SW + c * 4) * 4, A + (size_t)(row0 + r) * lda + kb + c * 8);
            cp16(sb + (r * SW + c * 4) * 4, B + (size_t)(col0 + r) * ldb + kb + c * 8);
        }
    };

    // prologue: 3 stages in flight
    issue(0, 0); cp_commit();
    issue(1, 1); cp_commit();
    issue(2, 2); cp_commit();

    for (int kt = 0; kt < KT; kt++) {
        asm volatile("cp.async.wait_group 2;" ::: "memory");
        __syncthreads();
        // slot (kt+3)&3 == (kt-1)&3: all warps finished kt-1 before the sync.
        if (kt + 3 < KT) issue((kt + 3) & 3, kt + 3);
        cp_commit();

        const uint32_t stg = sm0 + ((kt & 3) * 2 * TILE_W) * 4;

#pragma unroll
        for (int ks = 0; ks < 2; ks++) {            // two k16 steps per k32
            const uint32_t kb = stg + ks * 32;      // ks*8 words = 32 bytes
            uint32_t af[4][4], bq[4][4];
#pragma unroll
            for (int mt = 0; mt < 4; mt++) ldmx4(af[mt], kb + aOff[mt]);
#pragma unroll
            for (int p = 0; p < 4; p++)    ldmx4(bq[p], kb + bOff[p]);
#pragma unroll
            for (int mt = 0; mt < 4; mt++)
#pragma unroll
                for (int nt = 0; nt < 8; nt++)
                    mma_f16(acc[mt][nt], af[mt], &bq[nt >> 1][(nt & 1) * 2]);
        }
    }

    // Epilogue: c0/c1 at (row, 2*tig), c2/c3 at (row+8, 2*tig)
#pragma unroll
    for (int mt = 0; mt < 4; mt++) {
        const int r = row0 + wm + mt * 16 + gid;
        float inv0 = 1.0f, inv1 = 1.0f;
        if (DIV) { inv0 = 1.0f / rsum[r]; inv1 = 1.0f / rsum[r + 8]; }
        float s0 = 0.0f, s1 = 0.0f;
#pragma unroll
        for (int nt = 0; nt < 8; nt++) {
            const int c = col0 + wn + nt * 8 + 2 * tig;
            float o0 = acc[mt][nt][0] * scale, o1 = acc[mt][nt][1] * scale;
            float o2 = acc[mt][nt][2] * scale, o3 = acc[mt][nt][3] * scale;
            if (EPI == 2) {
                o0 = __expf(o0); o1 = __expf(o1);
                o2 = __expf(o2); o3 = __expf(o3);
            }
            if (EPI == 0) {
                float* C = (float*)Cv;
                if (DIV) { o0 *= inv0; o1 *= inv0; o2 *= inv1; o3 *= inv1; }
                *(float2*)(C + (size_t)r * ldc + c)       = make_float2(o0, o1);
                *(float2*)(C + (size_t)(r + 8) * ldc + c) = make_float2(o2, o3);
            } else if (EPI == 3) {
                float* C = (float*)Cv;
                if (DIV) { o0 *= inv0; o1 *= inv0; o2 *= inv1; o3 *= inv1; }
                atomicAdd(C + (size_t)r * ldc + c,           o0);
                atomicAdd(C + (size_t)r * ldc + c + 1,       o1);
                atomicAdd(C + (size_t)(r + 8) * ldc + c,     o2);
                atomicAdd(C + (size_t)(r + 8) * ldc + c + 1, o3);
            } else {
                __half* C = (__half*)Cv;
                __half2 h0 = __floats2half2_rn(o0, o1);
                __half2 h1 = __floats2half2_rn(o2, o3);
                *(__half2*)(C + (size_t)r * ldc + c)       = h0;
                *(__half2*)(C + (size_t)(r + 8) * ldc + c) = h1;
                if (EPI == 2) {   // accumulate rounded row-sums
                    float2 f0 = __half22float2(h0), f1 = __half22float2(h1);
                    s0 += f0.x + f0.y;
                    s1 += f1.x + f1.y;
                }
            }
        }
        if (EPI == 2) {
            // quad reduce (lanes of same gid: xor 1, 2)
            s0 += __shfl_xor_sync(0xffffffffu, s0, 1);
            s0 += __shfl_xor_sync(0xffffffffu, s0, 2);
            s1 += __shfl_xor_sync(0xffffffffu, s1, 1);
            s1 += __shfl_xor_sync(0xffffffffu, s1, 2);
            if (tig == 0) {
                atomicAdd(rsum + r, s0);
                atomicAdd(rsum + r + 8, s1);
            }
        }
    }
}

// Standard GEMM wrapper (2D grid)
template <int EPI, bool DIV>
__global__ __launch_bounds__(128, 2)
void gemm_h(const __half* __restrict__ A, const __half* __restrict__ B,
            void* __restrict__ Cv, int K, int lda, int ldb, int ldc,
            float scale, float* __restrict__ rsum)
{
    gemm_body<EPI, DIV>(A, B, Cv, K, lda, ldb, ldc, scale, rsum,
                        blockIdx.y * 128, blockIdx.x * 128);
}

// Split-K GEMM wrapper: grid.z slices the K range; each slice contributes an
// atomicAdd partial (EPI=3). Deterministic for gridDim.z == 2 (fp32 add of
// exactly two partials is order-independent).
template <int EPI, bool DIV>
__global__ __launch_bounds__(128, 2)
void gemm_hsk(const __half* __restrict__ A, const __half* __restrict__ B,
              void* __restrict__ Cv, int Ksub, int lda, int ldb, int ldc,
              float scale, float* __restrict__ rsum)
{
    const int kstart = blockIdx.z * Ksub;
    gemm_body<EPI, DIV>(A + kstart, B + kstart, Cv, Ksub, lda, ldb, ldc,
                        scale, rsum, blockIdx.y * 128, blockIdx.x * 128);
}

// Fused projections: bid < 512 -> [Q|K] = X @ [Wq;Wk]^T tile; bid >= 512 ->
// V^T = Wv @ X^T tile. Both K=1024, EPI=1.
__global__ __launch_bounds__(128, 2)
void proj_fused(const __half* __restrict__ xh, const __half* __restrict__ wqkh,
                const __half* __restrict__ wvh, __half* __restrict__ qkh,
                __half* __restrict__ vth)
{
    const int id = blockIdx.x;
    if (id < 512) {
        gemm_body<1, false>(xh, wqkh, qkh, DIM, DIM, DIM, 2 * DIM, 1.0f,
                            nullptr, (id >> 4) * 128, (id & 15) * 128);
    } else {
        const int j = id - 512;
        gemm_body<1, false>(wvh, xh, vth, DIM, DIM, DIM, SEQ, 1.0f,
                            nullptr, (j >> 5) * 128, (j & 31) * 128);
    }
}

// ---------------------------------------------------------------------------
extern "C" void kernel_launch(void* const* d_in, const int* in_sizes, int n_in,
                              void* d_out, int out_size)
{
    const float* x  = (const float*)d_in[0];
    const float* Wq = (const float*)d_in[1];
    const float* Wk = (const float*)d_in[2];
    const float* Wv = (const float*)d_in[3];
    float* out = (float*)d_out;

    __half *xh, *wqkh, *wvh, *qkh, *vth, *ph;
    float *rsp;
    cudaGetSymbolAddress((void**)&xh,   g_xh);
    cudaGetSymbolAddress((void**)&wqkh, g_wqkh);
    cudaGetSymbolAddress((void**)&wvh,  g_wvh);
    cudaGetSymbolAddress((void**)&qkh,  g_qkh);
    cudaGetSymbolAddress((void**)&vth,  g_vth);
    cudaGetSymbolAddress((void**)&ph,   g_ph);
    cudaGetSymbolAddress((void**)&rsp,  g_rsum);

    cudaFuncSetAttribute((const void*)proj_fused,
                         cudaFuncAttributeMaxDynamicSharedMemorySize, SMEM_BYTES);
    cudaFuncSetAttribute((const void*)gemm_h<2, false>,
                         cudaFuncAttributeMaxDynamicSharedMemorySize, SMEM_BYTES);
    cudaFuncSetAttribute((const void*)gemm_hsk<3, true>,
                         cudaFuncAttributeMaxDynamicSharedMemorySize, SMEM_BYTES);

    const float scale = 1.0f / 32.0f;  // 1/sqrt(1024)

    // fp32 -> fp16 conversion + rsum zero + out zero (one launch)
    cvt_all<<<(XN4 + 3 * WN4 + 255) / 256, 256>>>(x, Wq, Wk, Wv, xh, wqkh, wvh,
                                                  rsp, out);

    // [Q|K] projection (512 CTAs) + V^T projection (256 CTAs) in one launch
    proj_fused<<<768, 128, SMEM_BYTES>>>(xh, wqkh, wvh, qkh, vth);

    // P = exp((Q @ K^T) / 32)  fp16 (unnormalized) + rowsum atomics
    gemm_h<2, false><<<dim3(SEQ / 128, SEQ / 128), 128, SMEM_BYTES>>>(
        qkh, qkh + DIM, ph, DIM, 2 * DIM, 2 * DIM, SEQ, scale, rsp);

    // O = (P @ (V^T)^T) / rowsum   [4096, 1024] fp32, split-K=2 (512 CTAs)
    gemm_hsk<3, true><<<dim3(DIM / 128, SEQ / 128, 2), 128, SMEM_BYTES>>>(
        ph, vth, out, SEQ / 2, SEQ, SEQ, DIM, 1.0f, rsp);
}

// round 17
// speedup vs baseline: 1.0679x; 1.0679x over previous
#include <cuda_runtime.h>
#include <cuda_fp16.h>
#include <cstdint>
#include <math.h>

#define SEQ 4096
#define DIM 1024

// Scratch (allocation-free rule: device globals)
__device__ __half g_xh[SEQ * DIM];            // fp16 x
__device__ __half g_wqkh[2 * DIM * DIM];      // fp16 [Wq; Wk] packed
__device__ __half g_wvh[DIM * DIM];           // fp16 Wv
__device__ __half g_qkh[SEQ * 2 * DIM];       // [Q | K] fp16, ld = 2048
__device__ __half g_vth[(size_t)DIM * SEQ];   // V^T fp16 [1024, 4096]
__device__ __half g_ph[(size_t)SEQ * SEQ];    // exp(S) fp16 (unnormalized P)
__device__ float  g_rsum[SEQ];                // rowsum of P (atomic accum)

// ---------------------------------------------------------------------------
// PTX helpers (base-target-safe: cp.async + mma.sync + ldmatrix only)
// ---------------------------------------------------------------------------
__device__ __forceinline__ uint32_t smem_u32(const void* p) {
    uint32_t a;
    asm("{ .reg .u64 t; cvta.to.shared.u64 t, %1; cvt.u32.u64 %0, t; }" : "=r"(a) : "l"(p));
    return a;
}
__device__ __forceinline__ void cp16(uint32_t s, const void* g) {
    asm volatile("cp.async.cg.shared.global [%0], [%1], 16;" :: "r"(s), "l"(g));
}
__device__ __forceinline__ void cp_commit() {
    asm volatile("cp.async.commit_group;" ::: "memory");
}
__device__ __forceinline__ void ldmx4(uint32_t* r, uint32_t addr) {
    asm volatile("ldmatrix.sync.aligned.m8n8.x4.shared.b16 {%0,%1,%2,%3}, [%4];"
        : "=r"(r[0]), "=r"(r[1]), "=r"(r[2]), "=r"(r[3]) : "r"(addr));
}
__device__ __forceinline__ void mma_f16(float* c, const uint32_t* a, const uint32_t* b) {
    asm volatile(
        "mma.sync.aligned.m16n8k16.row.col.f32.f16.f16.f32 "
        "{%0,%1,%2,%3}, {%4,%5,%6,%7}, {%8,%9}, {%0,%1,%2,%3};"
        : "+f"(c[0]), "+f"(c[1]), "+f"(c[2]), "+f"(c[3])
        : "r"(a[0]), "r"(a[1]), "r"(a[2]), "r"(a[3]), "r"(b[0]), "r"(b[1]));
}
// raw ex2 (the MUFU op __expf lowers to, minus the log2e pre-multiply)
__device__ __forceinline__ float ex2f(float x) {
    float y;
    asm("ex2.approx.f32 %0, %1;" : "=f"(y) : "f"(x));
    return y;
}

// ---------------------------------------------------------------------------
// Merged fp32 -> fp16 conversion of x, Wq, Wk, Wv + rsum zeroing (one launch)
// ---------------------------------------------------------------------------
#define XN4   (SEQ * DIM / 4)      // 1048576
#define WN4   (DIM * DIM / 4)      // 262144
__global__ __launch_bounds__(256)
void cvt_all(const float* __restrict__ x,  const float* __restrict__ Wq,
             const float* __restrict__ Wk, const float* __restrict__ Wv,
             __half* __restrict__ xh, __half* __restrict__ wqkh,
             __half* __restrict__ wvh, float* __restrict__ rs)
{
    int i = blockIdx.x * 256 + threadIdx.x;
    if (i < SEQ) rs[i] = 0.0f;      // deterministic rsum zero for graph replay
    const float* src;
    __half* dst;
    int off;
    if (i < XN4)                 { src = x;  dst = xh;   off = i; }
    else if (i < XN4 + WN4)      { src = Wq; dst = wqkh; off = i - XN4; }
    else if (i < XN4 + 2 * WN4)  { src = Wk; dst = wqkh + DIM * DIM; off = i - XN4 - WN4; }
    else if (i < XN4 + 3 * WN4)  { src = Wv; dst = wvh;  off = i - XN4 - 2 * WN4; }
    else return;
    float4 v = ((const float4*)src)[off];
    __half2* o = (__half2*)dst + 2 * (size_t)off;
    o[0] = __floats2half2_rn(v.x, v.y);
    o[1] = __floats2half2_rn(v.z, v.w);
}

// ---------------------------------------------------------------------------
// fp16 mma.sync NT GEMM body: C[M,N] = epi(scale * A[M,K] * B^T)
// BM=BN=128, BK=32, 4-stage cp.async (1 sync/iter), 128 threads, 4 warps (2x2),
// 64x64 per warp, ldmatrix.x4 fragments, m16n8k16 HMMA, fp32 accumulate.
// 2 CTAs/SM. (PROVEN mainloop+grid — R5/R11/R12/R14/R15/R16 deviations all lost.)
// EPI: 0 = fp32 store, 1 = fp16 store,
//      2 = fp16 ex2(scale*acc) store + rowsum atomics (scale carries log2e).
// DIV: multiply output rows by 1/rsum[r] (EPI=0 path).
// ---------------------------------------------------------------------------
#define SW 20                       // smem words per 32-half row (16 used + 4 pad)
#define TILE_W (128 * SW)           // words per A (or B) tile = 2560
#define NSTG 4
#define SMEM_BYTES (NSTG * 2 * TILE_W * 4)   // 81920

template <int EPI, bool DIV>
__device__ __forceinline__
void gemm_body(const __half* __restrict__ A, const __half* __restrict__ B,
               void* __restrict__ Cv, int K, int lda, int ldb, int ldc,
               float scale, float* __restrict__ rsum, int row0, int col0)
{
    extern __shared__ float sm[];
    const int tid  = threadIdx.x;
    const int lane = tid & 31;
    const int wid  = tid >> 5;     // 0..3
    const int gid  = lane >> 2;    // 0..7
    const int tig  = lane & 3;     // 0..3
    const int wm   = (wid & 1) * 64;
    const int wn   = (wid >> 1) * 64;

    const uint32_t sm0 = smem_u32(sm);

    // ldmatrix per-lane address offsets (bytes), within a stage
    const int mat = lane >> 3;     // 0..3
    const int rim = lane & 7;      // row in 8x8 matrix
    uint32_t aOff[4], bOff[4];
#pragma unroll
    for (int mt = 0; mt < 4; mt++)  // A m16 tile: row += (mat&1)*8, kw += (mat>>1)*4
        aOff[mt] = (uint32_t)(((wm + mt * 16 + (mat & 1) * 8 + rim) * SW
                               + (mat >> 1) * 4) * 4);
#pragma unroll
    for (int p = 0; p < 4; p++)     // B nt-pair: row += (mat>>1)*8, kw += (mat&1)*4
        bOff[p] = (uint32_t)((TILE_W + (wn + p * 16 + (mat >> 1) * 8 + rim) * SW
                               + (mat & 1) * 4) * 4);

    float acc[4][8][4];
#pragma unroll
    for (int i = 0; i < 4; i++)
#pragma unroll
        for (int j = 0; j < 8; j++)
#pragma unroll
            for (int q = 0; q < 4; q++) acc[i][j][q] = 0.0f;

    const int KT = K >> 5;   // K / 32

    auto issue = [&](int slot, int kt) {
        const uint32_t sa = sm0 + (slot * 2 * TILE_W) * 4;
        const uint32_t sb = sa + TILE_W * 4;
        const int kb = kt * 32;
#pragma unroll
        for (int t = 0; t < 4; t++) {
            int idx = tid + t * 128;          // 0..511
            int r = idx >> 2, c = idx & 3;    // row, 16B-chunk
            cp16(sa + (r * SW + c * 4) * 4, A + (size_t)(row0 + r) * lda + kb + c * 8);
            cp16(sb + (r * SW + c * 4) * 4, B + (size_t)(col0 + r) * ldb + kb + c * 8);
        }
    };

    // prologue: 3 stages in flight
    issue(0, 0); cp_commit();
    issue(1, 1); cp_commit();
    issue(2, 2); cp_commit();

    for (int kt = 0; kt < KT; kt++) {
        asm volatile("cp.async.wait_group 2;" ::: "memory");
        __syncthreads();
        // slot (kt+3)&3 == (kt-1)&3: all warps finished kt-1 before the sync.
        if (kt + 3 < KT) issue((kt + 3) & 3, kt + 3);
        cp_commit();

        const uint32_t stg = sm0 + ((kt & 3) * 2 * TILE_W) * 4;

#pragma unroll
        for (int ks = 0; ks < 2; ks++) {            // two k16 steps per k32
            const uint32_t kb = stg + ks * 32;      // ks*8 words = 32 bytes
            uint32_t af[4][4], bq[4][4];
#pragma unroll
            for (int mt = 0; mt < 4; mt++) ldmx4(af[mt], kb + aOff[mt]);
#pragma unroll
            for (int p = 0; p < 4; p++)    ldmx4(bq[p], kb + bOff[p]);
#pragma unroll
            for (int mt = 0; mt < 4; mt++)
#pragma unroll
                for (int nt = 0; nt < 8; nt++)
                    mma_f16(acc[mt][nt], af[mt], &bq[nt >> 1][(nt & 1) * 2]);
        }
    }

    // Epilogue: c0/c1 at (row, 2*tig), c2/c3 at (row+8, 2*tig)
#pragma unroll
    for (int mt = 0; mt < 4; mt++) {
        const int r = row0 + wm + mt * 16 + gid;
        float inv0 = 1.0f, inv1 = 1.0f;
        if (DIV) { inv0 = 1.0f / rsum[r]; inv1 = 1.0f / rsum[r + 8]; }
        float s0 = 0.0f, s1 = 0.0f;
#pragma unroll
        for (int nt = 0; nt < 8; nt++) {
            const int c = col0 + wn + nt * 8 + 2 * tig;
            float o0 = acc[mt][nt][0] * scale, o1 = acc[mt][nt][1] * scale;
            float o2 = acc[mt][nt][2] * scale, o3 = acc[mt][nt][3] * scale;
            if (EPI == 2) {        // scale already includes log2(e)
                o0 = ex2f(o0); o1 = ex2f(o1);
                o2 = ex2f(o2); o3 = ex2f(o3);
            }
            if (EPI == 0) {
                float* C = (float*)Cv;
                if (DIV) { o0 *= inv0; o1 *= inv0; o2 *= inv1; o3 *= inv1; }
                *(float2*)(C + (size_t)r * ldc + c)       = make_float2(o0, o1);
                *(float2*)(C + (size_t)(r + 8) * ldc + c) = make_float2(o2, o3);
            } else {
                __half* C = (__half*)Cv;
                __half2 h0 = __floats2half2_rn(o0, o1);
                __half2 h1 = __floats2half2_rn(o2, o3);
                *(__half2*)(C + (size_t)r * ldc + c)       = h0;
                *(__half2*)(C + (size_t)(r + 8) * ldc + c) = h1;
                if (EPI == 2) {   // accumulate rounded row-sums
                    float2 f0 = __half22float2(h0), f1 = __half22float2(h1);
                    s0 += f0.x + f0.y;
                    s1 += f1.x + f1.y;
                }
            }
        }
        if (EPI == 2) {
            // quad reduce (lanes of same gid: xor 1, 2)
            s0 += __shfl_xor_sync(0xffffffffu, s0, 1);
            s0 += __shfl_xor_sync(0xffffffffu, s0, 2);
            s1 += __shfl_xor_sync(0xffffffffu, s1, 1);
            s1 += __shfl_xor_sync(0xffffffffu, s1, 2);
            if (tig == 0) {
                atomicAdd(rsum + r, s0);
                atomicAdd(rsum + r + 8, s1);
            }
        }
    }
}

// Standard GEMM wrapper (2D grid)
template <int EPI, bool DIV>
__global__ __launch_bounds__(128, 2)
void gemm_h(const __half* __restrict__ A, const __half* __restrict__ B,
            void* __restrict__ Cv, int K, int lda, int ldb, int ldc,
            float scale, float* __restrict__ rsum)
{
    gemm_body<EPI, DIV>(A, B, Cv, K, lda, ldb, ldc, scale, rsum,
                        blockIdx.y * 128, blockIdx.x * 128);
}

// Fused projections: bid < 512 -> [Q|K] = X @ [Wq;Wk]^T tile; bid >= 512 ->
// V^T = Wv @ X^T tile. Both K=1024, EPI=1.
__global__ __launch_bounds__(128, 2)
void proj_fused(const __half* __restrict__ xh, const __half* __restrict__ wqkh,
                const __half* __restrict__ wvh, __half* __restrict__ qkh,
                __half* __restrict__ vth)
{
    const int id = blockIdx.x;
    if (id < 512) {
        gemm_body<1, false>(xh, wqkh, qkh, DIM, DIM, DIM, 2 * DIM, 1.0f,
                            nullptr, (id >> 4) * 128, (id & 15) * 128);
    } else {
        const int j = id - 512;
        gemm_body<1, false>(wvh, xh, vth, DIM, DIM, DIM, SEQ, 1.0f,
                            nullptr, (j >> 5) * 128, (j & 31) * 128);
    }
}

// ---------------------------------------------------------------------------
extern "C" void kernel_launch(void* const* d_in, const int* in_sizes, int n_in,
                              void* d_out, int out_size)
{
    const float* x  = (const float*)d_in[0];
    const float* Wq = (const float*)d_in[1];
    const float* Wk = (const float*)d_in[2];
    const float* Wv = (const float*)d_in[3];
    float* out = (float*)d_out;

    __half *xh, *wqkh, *wvh, *qkh, *vth, *ph;
    float *rsp;
    cudaGetSymbolAddress((void**)&xh,   g_xh);
    cudaGetSymbolAddress((void**)&wqkh, g_wqkh);
    cudaGetSymbolAddress((void**)&wvh,  g_wvh);
    cudaGetSymbolAddress((void**)&qkh,  g_qkh);
    cudaGetSymbolAddress((void**)&vth,  g_vth);
    cudaGetSymbolAddress((void**)&ph,   g_ph);
    cudaGetSymbolAddress((void**)&rsp,  g_rsum);

    cudaFuncSetAttribute((const void*)proj_fused,
                         cudaFuncAttributeMaxDynamicSharedMemorySize, SMEM_BYTES);
    cudaFuncSetAttribute((const void*)gemm_h<2, false>,
                         cudaFuncAttributeMaxDynamicSharedMemorySize, SMEM_BYTES);
    cudaFuncSetAttribute((const void*)gemm_h<0, true>,
                         cudaFuncAttributeMaxDynamicSharedMemorySize, SMEM_BYTES);

    // exp(s/32) = ex2(s * log2(e)/32): fold log2e into the S-GEMM scale
    const float scale_s = 1.4426950408889634f / 32.0f;

    // fp32 -> fp16 conversion + rsum zeroing (one launch)
    cvt_all<<<(XN4 + 3 * WN4 + 255) / 256, 256>>>(x, Wq, Wk, Wv, xh, wqkh, wvh, rsp);

    // [Q|K] projection (512 CTAs) + V^T projection (256 CTAs) in one launch
    proj_fused<<<768, 128, SMEM_BYTES>>>(xh, wqkh, wvh, qkh, vth);

    // P = ex2((Q @ K^T) * log2e/32)  fp16 (unnormalized) + rowsum atomics
    gemm_h<2, false><<<dim3(SEQ / 128, SEQ / 128), 128, SMEM_BYTES>>>(
        qkh, qkh + DIM, ph, DIM, 2 * DIM, 2 * DIM, SEQ, scale_s, rsp);

    // O = (P @ (V^T)^T) / rowsum   [4096, 1024] fp32
    gemm_h<0, true><<<dim3(DIM / 128, SEQ / 128), 128, SMEM_BYTES>>>(
        ph, vth, out, SEQ, SEQ, SEQ, DIM, 1.0f, rsp);
}